// round 2
// baseline (speedup 1.0000x reference)
#include <cuda_runtime.h>
#include <cstdint>

// Problem constants (fixed shapes for this problem instance)
#define NB      4
#define NNODES  50000
#define DIN     128
#define DOUT    64
#define NEDGES  800000
#define MTOTAL  (NB * NNODES)          // 200000 flattened GEMM rows

// ---------------- device scratch (no cudaMalloc allowed) ----------------
__device__ float g_pre[NB * NNODES * DOUT];   // 51.2 MB: x @ W
__device__ int   g_counts[NNODES];
__device__ int   g_offs[NNODES + 1];
__device__ int   g_cursor[NNODES];
__device__ int   g_scol[NEDGES];
__device__ float g_sval[NEDGES];

// ---------------- CSR build ----------------
__global__ void zero_counts_kernel() {
    int i = blockIdx.x * blockDim.x + threadIdx.x;
    if (i < NNODES) g_counts[i] = 0;
}

__global__ void hist_kernel(const int* __restrict__ erows) {
    int e = blockIdx.x * blockDim.x + threadIdx.x;
    if (e < NEDGES) atomicAdd(&g_counts[erows[e]], 1);
}

// single-block chunked inclusive scan -> offsets + scatter cursors
__global__ void scan_kernel() {
    __shared__ int sm[1024];
    __shared__ int carry_s;
    int tid = threadIdx.x;
    if (tid == 0) carry_s = 0;
    __syncthreads();
    for (int base = 0; base < NNODES; base += 1024) {
        int i = base + tid;
        int v = (i < NNODES) ? g_counts[i] : 0;
        sm[tid] = v;
        __syncthreads();
        #pragma unroll
        for (int off = 1; off < 1024; off <<= 1) {
            int add = (tid >= off) ? sm[tid - off] : 0;
            __syncthreads();
            sm[tid] += add;
            __syncthreads();
        }
        int inc = sm[tid] + carry_s;
        if (i < NNODES) {
            g_offs[i + 1] = inc;
            g_cursor[i]   = inc - v;   // exclusive start
        }
        __syncthreads();
        if (tid == 1023) carry_s = inc;
        __syncthreads();
    }
    if (tid == 0) g_offs[0] = 0;
}

__global__ void scatter_kernel(const int* __restrict__ erows,
                               const int* __restrict__ ecols,
                               const float* __restrict__ evals) {
    int e = blockIdx.x * blockDim.x + threadIdx.x;
    if (e < NEDGES) {
        int r = erows[e];
        int pos = atomicAdd(&g_cursor[r], 1);
        g_scol[pos] = ecols[e];
        g_sval[pos] = evals[e];
    }
}

// ---------------- GEMM: pre[m, 0:64] = x[m, 0:128] @ W ----------------
// 256 threads (16x16), 64x64 output tile, K chunked by 64.
__global__ void gemm_kernel(const float* __restrict__ x,
                            const float* __restrict__ w) {
    __shared__ float xs[64][68];   // [row][k], padded
    __shared__ float ws[64][64];   // [k][col]
    int t  = threadIdx.x;
    int tx = t & 15;          // col group
    int ty = t >> 4;          // row group
    int rowBase = blockIdx.x * 64;

    float acc[4][4] = {};

    for (int kc = 0; kc < DIN; kc += 64) {
        #pragma unroll
        for (int i = 0; i < 4; i++) {
            int idx = t + i * 256;
            int r  = idx >> 4;
            int kq = idx & 15;
            float4 v = *reinterpret_cast<const float4*>(
                x + (size_t)(rowBase + r) * DIN + kc + kq * 4);
            *reinterpret_cast<float4*>(&xs[r][kq * 4]) = v;
        }
        #pragma unroll
        for (int i = 0; i < 4; i++) {
            int idx = t + i * 256;
            int kr = idx >> 4;
            int kq = idx & 15;
            float4 v = *reinterpret_cast<const float4*>(
                w + (size_t)(kc + kr) * DOUT + kq * 4);
            *reinterpret_cast<float4*>(&ws[kr][kq * 4]) = v;
        }
        __syncthreads();
        #pragma unroll
        for (int k = 0; k < 64; k++) {
            float4 wv = *reinterpret_cast<const float4*>(&ws[k][tx * 4]);
            float xv[4];
            #pragma unroll
            for (int j = 0; j < 4; j++) xv[j] = xs[ty * 4 + j][k];
            #pragma unroll
            for (int j = 0; j < 4; j++) {
                acc[j][0] += xv[j] * wv.x;
                acc[j][1] += xv[j] * wv.y;
                acc[j][2] += xv[j] * wv.z;
                acc[j][3] += xv[j] * wv.w;
            }
        }
        __syncthreads();
    }

    #pragma unroll
    for (int j = 0; j < 4; j++) {
        size_t r = (size_t)rowBase + ty * 4 + j;
        *reinterpret_cast<float4*>(g_pre + r * DOUT + tx * 4) =
            make_float4(acc[j][0], acc[j][1], acc[j][2], acc[j][3]);
    }
}

// ---------------- aggregation: warp per destination row, all 4 batches ----------------
__global__ void aggregate_kernel(float* __restrict__ out) {
    int gwarp = (blockIdx.x * blockDim.x + threadIdx.x) >> 5;
    int lane  = threadIdx.x & 31;
    if (gwarp >= NNODES) return;

    int start = g_offs[gwarp];
    int end   = g_offs[gwarp + 1];

    float2 a0 = make_float2(0.f, 0.f), a1 = a0, a2 = a0, a3 = a0;
    const float2* p2 = reinterpret_cast<const float2*>(g_pre);
    const size_t bstride = (size_t)NNODES * (DOUT / 2);   // float2 per batch

    for (int i = start; i < end; i++) {
        int   c = g_scol[i];
        float v = g_sval[i];
        size_t base = (size_t)c * (DOUT / 2) + lane;
        float2 p;
        p = p2[base];               a0.x += v * p.x; a0.y += v * p.y;
        p = p2[base +     bstride]; a1.x += v * p.x; a1.y += v * p.y;
        p = p2[base + 2 * bstride]; a2.x += v * p.x; a2.y += v * p.y;
        p = p2[base + 3 * bstride]; a3.x += v * p.x; a3.y += v * p.y;
    }

    float2* o2 = reinterpret_cast<float2*>(out);
    size_t ob = (size_t)gwarp * (DOUT / 2) + lane;
    o2[ob]               = make_float2(fmaxf(a0.x, 0.f), fmaxf(a0.y, 0.f));
    o2[ob +     bstride] = make_float2(fmaxf(a1.x, 0.f), fmaxf(a1.y, 0.f));
    o2[ob + 2 * bstride] = make_float2(fmaxf(a2.x, 0.f), fmaxf(a2.y, 0.f));
    o2[ob + 3 * bstride] = make_float2(fmaxf(a3.x, 0.f), fmaxf(a3.y, 0.f));
}

// ---------------- launch ----------------
extern "C" void kernel_launch(void* const* d_in, const int* in_sizes, int n_in,
                              void* d_out, int out_size) {
    const float* x     = (const float*)d_in[0];   // [4, 50000, 128]
    const float* w     = (const float*)d_in[1];   // [128, 64]
    const float* evals = (const float*)d_in[2];   // [800000]
    const int*   erows = (const int*)  d_in[3];   // [800000]
    const int*   ecols = (const int*)  d_in[4];   // [800000]
    float* out = (float*)d_out;                   // [4, 50000, 64]

    (void)in_sizes; (void)n_in; (void)out_size;

    // CSR build
    zero_counts_kernel<<<(NNODES + 255) / 256, 256>>>();
    hist_kernel<<<NEDGES / 256, 256>>>(erows);
    scan_kernel<<<1, 1024>>>();
    scatter_kernel<<<NEDGES / 256, 256>>>(erows, ecols, evals);

    // dense GEMM
    gemm_kernel<<<MTOTAL / 64, 256>>>(x, w);

    // gather/scale/segment-sum/relu
    aggregate_kernel<<<(NNODES * 32 + 255) / 256, 256>>>(out);
}

// round 3
// speedup vs baseline: 1.2882x; 1.2882x over previous
#include <cuda_runtime.h>
#include <cuda_fp16.h>
#include <cstdint>

#define NB      4
#define NNODES  50000
#define DIN     128
#define DOUT    64
#define NEDGES  800000
#define MTOTAL  (NB * NNODES)

// ---------------- device scratch ----------------
__device__ __half g_preh[NB * NNODES * DOUT];   // 25.6 MB: fp16(x @ W)
__device__ int   g_counts[NNODES];
__device__ int   g_offs[NNODES + 1];
__device__ int   g_cursor[NNODES];
__device__ int   g_scol[NEDGES];
__device__ float g_sval[NEDGES];

// ---------------- packed f32x2 helpers ----------------
__device__ __forceinline__ void ffma2(unsigned long long& d,
                                      unsigned long long a,
                                      unsigned long long b) {
    asm("fma.rn.f32x2 %0, %1, %2, %0;" : "+l"(d) : "l"(a), "l"(b));
}
__device__ __forceinline__ unsigned long long pack2(float x) {
    unsigned long long r;
    asm("mov.b64 %0, {%1, %1};" : "=l"(r) : "f"(x));
    return r;
}
__device__ __forceinline__ float2 unpack2(unsigned long long a) {
    float lo, hi;
    asm("mov.b64 {%0, %1}, %2;" : "=f"(lo), "=f"(hi) : "l"(a));
    return make_float2(lo, hi);
}

// ---------------- CSR build ----------------
__global__ void zero_counts_kernel() {
    int i = blockIdx.x * blockDim.x + threadIdx.x;
    if (i < NNODES) g_counts[i] = 0;
}

__global__ void hist_kernel(const int* __restrict__ erows) {
    int e = blockIdx.x * blockDim.x + threadIdx.x;
    if (e < NEDGES) atomicAdd(&g_counts[erows[e]], 1);
}

// single-block scan: shuffle-based, 4 elems/thread, 4096 per chunk
__global__ void scan_kernel() {
    __shared__ int wsum[32];
    __shared__ int s_carry;
    __shared__ int s_total;
    int tid = threadIdx.x, lane = tid & 31, wid = tid >> 5;
    if (tid == 0) s_carry = 0;
    __syncthreads();

    for (int base = 0; base < NNODES; base += 4096) {
        int i0 = base + tid * 4;
        int v0 = (i0 + 0 < NNODES) ? g_counts[i0 + 0] : 0;
        int v1 = (i0 + 1 < NNODES) ? g_counts[i0 + 1] : 0;
        int v2 = (i0 + 2 < NNODES) ? g_counts[i0 + 2] : 0;
        int v3 = (i0 + 3 < NNODES) ? g_counts[i0 + 3] : 0;
        int c0 = v0, c1 = c0 + v1, c2 = c1 + v2, c3 = c2 + v3;

        int s = c3;
        #pragma unroll
        for (int off = 1; off < 32; off <<= 1) {
            int n = __shfl_up_sync(0xffffffffu, s, off);
            if (lane >= off) s += n;
        }
        if (lane == 31) wsum[wid] = s;
        __syncthreads();
        if (wid == 0) {
            int t = wsum[lane];
            #pragma unroll
            for (int off = 1; off < 32; off <<= 1) {
                int n = __shfl_up_sync(0xffffffffu, t, off);
                if (lane >= off) t += n;
            }
            wsum[lane] = t;
            if (lane == 31) s_total = t;
        }
        __syncthreads();

        int excl = s_carry + (wid > 0 ? wsum[wid - 1] : 0) + (s - c3);
        if (i0 + 0 < NNODES) { g_offs[i0 + 1] = excl + c0; g_cursor[i0 + 0] = excl; }
        if (i0 + 1 < NNODES) { g_offs[i0 + 2] = excl + c1; g_cursor[i0 + 1] = excl + c0; }
        if (i0 + 2 < NNODES) { g_offs[i0 + 3] = excl + c2; g_cursor[i0 + 2] = excl + c1; }
        if (i0 + 3 < NNODES) { g_offs[i0 + 4] = excl + c3; g_cursor[i0 + 3] = excl + c2; }
        __syncthreads();
        if (tid == 0) s_carry += s_total;
        __syncthreads();
    }
    if (threadIdx.x == 0) g_offs[0] = 0;
}

__global__ void scatter_kernel(const int* __restrict__ erows,
                               const int* __restrict__ ecols,
                               const float* __restrict__ evals) {
    int e = blockIdx.x * blockDim.x + threadIdx.x;
    if (e < NEDGES) {
        int r = erows[e];
        int pos = atomicAdd(&g_cursor[r], 1);
        g_scol[pos] = ecols[e];
        g_sval[pos] = evals[e];
    }
}

// ---------------- GEMM: pre = x @ W, fp32 math via f32x2, fp16 output ----------------
__global__ void gemm_kernel(const float* __restrict__ x,
                            const float* __restrict__ w) {
    __shared__ float xs[64][68];
    __shared__ float ws[64][64];
    int t  = threadIdx.x;
    int tx = t & 15;
    int ty = t >> 4;
    int rowBase = blockIdx.x * 64;

    unsigned long long acc2[4][2] = {};   // 0ull == {0.0f, 0.0f}

    for (int kc = 0; kc < DIN; kc += 64) {
        #pragma unroll
        for (int i = 0; i < 4; i++) {
            int idx = t + i * 256;
            int r  = idx >> 4;
            int kq = idx & 15;
            float4 v = *reinterpret_cast<const float4*>(
                x + (size_t)(rowBase + r) * DIN + kc + kq * 4);
            *reinterpret_cast<float4*>(&xs[r][kq * 4]) = v;
        }
        #pragma unroll
        for (int i = 0; i < 4; i++) {
            int idx = t + i * 256;
            int kr = idx >> 4;
            int kq = idx & 15;
            float4 v = *reinterpret_cast<const float4*>(
                w + (size_t)(kc + kr) * DOUT + kq * 4);
            *reinterpret_cast<float4*>(&ws[kr][kq * 4]) = v;
        }
        __syncthreads();
        #pragma unroll
        for (int k = 0; k < 64; k++) {
            ulonglong2 lw = *reinterpret_cast<const ulonglong2*>(&ws[k][tx * 4]);
            #pragma unroll
            for (int j = 0; j < 4; j++) {
                unsigned long long xp = pack2(xs[ty * 4 + j][k]);
                ffma2(acc2[j][0], xp, lw.x);
                ffma2(acc2[j][1], xp, lw.y);
            }
        }
        __syncthreads();
    }

    #pragma unroll
    for (int j = 0; j < 4; j++) {
        size_t r = (size_t)rowBase + ty * 4 + j;
        float2 f0 = unpack2(acc2[j][0]);
        float2 f1 = unpack2(acc2[j][1]);
        __half2* ph = reinterpret_cast<__half2*>(g_preh + r * DOUT + tx * 4);
        ph[0] = __floats2half2_rn(f0.x, f0.y);
        ph[1] = __floats2half2_rn(f1.x, f1.y);
    }
}

// ---------------- aggregation: warp per destination row, fp16 pre, fp32 accum ----------------
__global__ void aggregate_kernel(float* __restrict__ out) {
    int gwarp = (blockIdx.x * blockDim.x + threadIdx.x) >> 5;
    int lane  = threadIdx.x & 31;
    if (gwarp >= NNODES) return;

    int start = g_offs[gwarp];
    int end   = g_offs[gwarp + 1];

    float2 a0 = make_float2(0.f, 0.f), a1 = a0, a2 = a0, a3 = a0;
    const __half2* p2 = reinterpret_cast<const __half2*>(g_preh);
    const size_t bstride = (size_t)NNODES * (DOUT / 2);

    for (int i = start; i < end; i++) {
        int   c = g_scol[i];
        float v = g_sval[i];
        size_t base = (size_t)c * (DOUT / 2) + lane;
        float2 f;
        f = __half22float2(p2[base]);               a0.x += v * f.x; a0.y += v * f.y;
        f = __half22float2(p2[base +     bstride]); a1.x += v * f.x; a1.y += v * f.y;
        f = __half22float2(p2[base + 2 * bstride]); a2.x += v * f.x; a2.y += v * f.y;
        f = __half22float2(p2[base + 3 * bstride]); a3.x += v * f.x; a3.y += v * f.y;
    }

    float2* o2 = reinterpret_cast<float2*>(out);
    size_t ob = (size_t)gwarp * (DOUT / 2) + lane;
    o2[ob]               = make_float2(fmaxf(a0.x, 0.f), fmaxf(a0.y, 0.f));
    o2[ob +     bstride] = make_float2(fmaxf(a1.x, 0.f), fmaxf(a1.y, 0.f));
    o2[ob + 2 * bstride] = make_float2(fmaxf(a2.x, 0.f), fmaxf(a2.y, 0.f));
    o2[ob + 3 * bstride] = make_float2(fmaxf(a3.x, 0.f), fmaxf(a3.y, 0.f));
}

// ---------------- launch ----------------
extern "C" void kernel_launch(void* const* d_in, const int* in_sizes, int n_in,
                              void* d_out, int out_size) {
    const float* x     = (const float*)d_in[0];
    const float* w     = (const float*)d_in[1];
    const float* evals = (const float*)d_in[2];
    const int*   erows = (const int*)  d_in[3];
    const int*   ecols = (const int*)  d_in[4];
    float* out = (float*)d_out;

    (void)in_sizes; (void)n_in; (void)out_size;

    zero_counts_kernel<<<(NNODES + 255) / 256, 256>>>();
    hist_kernel<<<NEDGES / 256, 256>>>(erows);
    scan_kernel<<<1, 1024>>>();
    scatter_kernel<<<NEDGES / 256, 256>>>(erows, ecols, evals);

    gemm_kernel<<<MTOTAL / 64, 256>>>(x, w);

    aggregate_kernel<<<(NNODES * 32 + 255) / 256, 256>>>(out);
}